// round 9
// baseline (speedup 1.0000x reference)
#include <cuda_runtime.h>
#include <cstdint>

// InteractingSites: per-frame all-pairs soft-core Coulomb.
// XOR-16 PACKED edition: f32x2 math where lo/hi halves carry rotations r and
// r+16 of the SAME frame. One u64 shuffle delivers both halves; no repacking
// inside the loop. Charge-zero masks kill duplicate/self pairs.
//
// energy[f] = sum_{i<j} q_i q_j * rsqrt(|p_i-p_j|^2 + 1e-6)
//
// CTA = 1 frame = 4 warps x 32. Tiles T0..T3 (32 sites each). Lane l holds:
//   P*_k  = packed ( T_k[l],  T_k[l^16] )      (shuffle source)
//   nR*_k = packed (-T_k[l], -T_k[l]    )      (duplicated negated row)
// shfl64(P_k, l+r) = ( T_k[(l+r)%32], T_k[(l+r+16)%32] )  -> rotations r, r+16.
//
// Enumeration (each unordered pair exactly once):
//  Rectangles: packed rotations r = 0..15 (x2 halves = 0..31). Warp w:
//    r in [4w, 4w+4). Per rotation, 6 tile combos (a<b), mobile tiles 1,2,3.
//  Triangles (per tile k): packed dd = 1..8 — lo covers rot dd, hi covers
//    rot dd+16; unordered that's rots {1..8} ∪ {15..9}; dd=8's hi duplicates
//    rot 8 -> zero hi charge. Plus packed dd=16 unit: lo = rot 16 (keep lanes
//    0..15 only), hi = rot 0 = self-pairs (always zeroed).
//    Warp w: dd in {w+1, w+5} for ALL tiles, + tile w's dd=16 unit.
//
// Charge factoring: acc_k += q_j * rsqrt (packed); row charge q_k applied once.

#define S_SITES 128
#define EPS2_PACKED 0x358637BD358637BDULL  // (1e-6f, 1e-6f)
#define FULLMASK 0xFFFFFFFFu

using u64 = unsigned long long;

__device__ __forceinline__ u64 pk2(float lo, float hi) {
    u64 r;
    asm("mov.b64 %0, {%1, %2};" : "=l"(r) : "f"(lo), "f"(hi));
    return r;
}
__device__ __forceinline__ void unpk2(u64 v, float& lo, float& hi) {
    asm("mov.b64 {%0, %1}, %2;" : "=f"(lo), "=f"(hi) : "l"(v));
}
__device__ __forceinline__ u64 add2(u64 a, u64 b) {
    u64 d;
    asm("add.rn.f32x2 %0, %1, %2;" : "=l"(d) : "l"(a), "l"(b));
    return d;
}
__device__ __forceinline__ u64 fma2(u64 a, u64 b, u64 c) {
    u64 d;
    asm("fma.rn.f32x2 %0, %1, %2, %3;" : "=l"(d) : "l"(a), "l"(b), "l"(c));
    return d;
}
__device__ __forceinline__ float frsqrt(float x) {
    float r;
    asm("rsqrt.approx.f32 %0, %1;" : "=f"(r) : "f"(x));
    return r;
}
__device__ __forceinline__ u64 shfl64(u64 v, int src) {
    return (u64)__shfl_sync(FULLMASK, (unsigned long long)v, src);
}

// acc += jq * rsqrt(|j + nrow|^2 + eps)   (nrow holds negated row coords)
__device__ __forceinline__ void grp(u64 nrx, u64 nry, u64 nrz,
                                    u64 jx, u64 jy, u64 jz, u64 jq,
                                    u64& acc) {
    u64 dx = add2(jx, nrx);
    u64 dy = add2(jy, nry);
    u64 dz = add2(jz, nrz);
    u64 r2 = fma2(dz, dz, (u64)EPS2_PACKED);
    r2 = fma2(dy, dy, r2);
    r2 = fma2(dx, dx, r2);
    float rl, rh;
    unpk2(r2, rl, rh);
    u64 rs = pk2(frsqrt(rl), frsqrt(rh));
    acc = fma2(jq, rs, acc);
}

__global__ __launch_bounds__(S_SITES)
void interacting_sites_kernel(const float* __restrict__ positions,
                              const float* __restrict__ charges,
                              float* __restrict__ out) {
    __shared__ float warp_sum[4];

    const int fid = blockIdx.x;
    const int w = threadIdx.x >> 5;
    const int l = threadIdx.x & 31;

    // Load lane's 4 sites and build packed registers
    const long long base = (long long)fid * S_SITES;
    u64 Px[4], Py[4], Pz[4], Pq[4];      // (val[l], val[l^16])
    u64 nRx[4], nRy[4], nRz[4];          // (-val[l], -val[l])
    float sq[4];                          // row charges
#pragma unroll
    for (int k = 0; k < 4; ++k) {
        const long long idx = base + k * 32 + l;
        const float* p = positions + idx * 3;
        const float x = p[0], y = p[1], z = p[2], q = charges[idx];
        const float xo = __shfl_xor_sync(FULLMASK, x, 16);
        const float yo = __shfl_xor_sync(FULLMASK, y, 16);
        const float zo = __shfl_xor_sync(FULLMASK, z, 16);
        const float qo = __shfl_xor_sync(FULLMASK, q, 16);
        Px[k] = pk2(x, xo);
        Py[k] = pk2(y, yo);
        Pz[k] = pk2(z, zo);
        Pq[k] = pk2(q, qo);
        nRx[k] = pk2(-x, -x);
        nRy[k] = pk2(-y, -y);
        nRz[k] = pk2(-z, -z);
        sq[k] = q;
    }

    u64 acc[4] = {0ULL, 0ULL, 0ULL, 0ULL};

    // ── Rectangles: warp w handles packed rotations r in [4w, 4w+4) ──
#pragma unroll
    for (int i = 0; i < 4; ++i) {
        const int src = l + (w << 2) + i;   // shfl wraps mod 32

        const u64 j1x = shfl64(Px[1], src), j1y = shfl64(Py[1], src),
                  j1z = shfl64(Pz[1], src), j1q = shfl64(Pq[1], src);
        const u64 j2x = shfl64(Px[2], src), j2y = shfl64(Py[2], src),
                  j2z = shfl64(Pz[2], src), j2q = shfl64(Pq[2], src);
        const u64 j3x = shfl64(Px[3], src), j3y = shfl64(Py[3], src),
                  j3z = shfl64(Pz[3], src), j3q = shfl64(Pq[3], src);

        grp(nRx[0], nRy[0], nRz[0], j1x, j1y, j1z, j1q, acc[0]);
        grp(nRx[0], nRy[0], nRz[0], j2x, j2y, j2z, j2q, acc[0]);
        grp(nRx[0], nRy[0], nRz[0], j3x, j3y, j3z, j3q, acc[0]);
        grp(nRx[1], nRy[1], nRz[1], j2x, j2y, j2z, j2q, acc[1]);
        grp(nRx[1], nRy[1], nRz[1], j3x, j3y, j3z, j3q, acc[1]);
        grp(nRx[2], nRy[2], nRz[2], j3x, j3y, j3z, j3q, acc[2]);
    }

    // ── Triangles: warp w handles packed dd in {w+1, w+5} for all tiles ──
#pragma unroll
    for (int ii = 0; ii < 2; ++ii) {
        const int dd = w + 1 + (ii << 2);          // 1..8 across 4 warps
        const int src = l + dd;
        // dd=8: hi half (rot 24 ≡ rot 8) duplicates the lo half -> zero hi q
        const u64 qmask = (dd == 8) ? 0x00000000FFFFFFFFULL : ~0ULL;
#pragma unroll
        for (int k = 0; k < 4; ++k) {
            const u64 jx = shfl64(Px[k], src);
            const u64 jy = shfl64(Py[k], src);
            const u64 jz = shfl64(Pz[k], src);
            const u64 jq = shfl64(Pq[k], src) & qmask;
            grp(nRx[k], nRy[k], nRz[k], jx, jy, jz, jq, acc[k]);
        }
    }
    // dd=16 unit for tile w: lo = rot 16 (lanes 0..15 only), hi = self (drop)
    {
        const int src = l + 16;
        const u64 qmask = (l < 16) ? 0x00000000FFFFFFFFULL : 0ULL;
        // dynamic tile index w -> unroll with guard to stay in registers
#pragma unroll
        for (int k = 0; k < 4; ++k) {
            if (k == w) {
                const u64 jx = shfl64(Px[k], src);
                const u64 jy = shfl64(Py[k], src);
                const u64 jz = shfl64(Pz[k], src);
                const u64 jq = shfl64(Pq[k], src) & qmask;
                grp(nRx[k], nRy[k], nRz[k], jx, jy, jz, jq, acc[k]);
            }
        }
    }

    // Row charges applied once; halves merged; lane -> warp -> CTA reduction
    float s = 0.f;
#pragma unroll
    for (int k = 0; k < 4; ++k) {
        float alo, ahi;
        unpk2(acc[k], alo, ahi);
        s = fmaf(sq[k], alo + ahi, s);
    }
#pragma unroll
    for (int o = 16; o > 0; o >>= 1)
        s += __shfl_xor_sync(FULLMASK, s, o);
    if (l == 0) warp_sum[w] = s;
    __syncthreads();
    if (threadIdx.x == 0)
        out[fid] = (warp_sum[0] + warp_sum[1]) + (warp_sum[2] + warp_sum[3]);
}

extern "C" void kernel_launch(void* const* d_in, const int* in_sizes, int n_in,
                              void* d_out, int out_size) {
    const float* positions = (const float*)d_in[0];  // [N,3] f32
    const float* charges   = (const float*)d_in[1];  // [N]   f32
    float* out = (float*)d_out;                      // [B]   f32

    const int num_frames = out_size;
    interacting_sites_kernel<<<num_frames, S_SITES>>>(positions, charges, out);
}

// round 10
// speedup vs baseline: 1.0021x; 1.0021x over previous
#include <cuda_runtime.h>
#include <cstdint>

// InteractingSites: per-frame all-pairs soft-core Coulomb — minimal-SASS edition.
//
// energy[f] = sum_{i<j} q_i q_j * rsqrt(|p_i-p_j|^2 + 1e-6)
//
// One CTA per frame, 128 threads (= sites). Site table (x,y,z,q) as float4 in
// shared, duplicated to 256 entries so site[t+d] needs no modulo. Thread t
// covers cyclic offsets d=1..63 (all threads) + d=64 (threads 0..63): each
// unordered pair exactly once, perfectly balanced (63/64 pairs per thread).
//
// FULL UNROLL: every LDS.128 gets an immediate offset (base + 16*d) — zero
// per-iteration address arithmetic or branches. Charge factoring: accumulate
// sum_j q_j * rsqrt(...), multiply by q_i once at the end. Two accumulators
// for dependency-chain ILP. ~9 SASS inst per pair.

#define S_SITES 128
#define EPS_SOFT 1e-6f
#define FULLMASK 0xFFFFFFFFu

__device__ __forceinline__ float frsqrt(float x) {
    float r;
    asm("rsqrt.approx.f32 %0, %1;" : "=f"(r) : "f"(x));
    return r;
}

__global__ __launch_bounds__(S_SITES)
void interacting_sites_kernel(const float* __restrict__ positions,
                              const float* __restrict__ charges,
                              float* __restrict__ out) {
    __shared__ float4 site[2 * S_SITES];
    __shared__ float warp_sum[4];

    const int f = blockIdx.x;
    const int t = threadIdx.x;

    // Load this thread's site: positions [N,3] row-major, charges [N].
    const long long base = (long long)f * S_SITES;
    const float* p = positions + (base + t) * 3;
    float4 v;
    v.x = p[0];
    v.y = p[1];
    v.z = p[2];
    v.w = charges[base + t];
    site[t] = v;
    site[t + S_SITES] = v;
    __syncthreads();

    const float px = v.x, py = v.y, pz = v.z, qi = v.w;
    float acc0 = 0.0f, acc1 = 0.0f;

    // d = 1..62 in pairs (two independent accumulator chains), fully unrolled:
    // site[t+d] compiles to LDS.128 [Rbase + 16*d] — immediate offsets only.
#pragma unroll
    for (int d = 1; d < 63; d += 2) {
        {
            const float4 s = site[t + d];
            const float dx = px - s.x;
            const float dy = py - s.y;
            const float dz = pz - s.z;
            const float r2 = fmaf(dx, dx, fmaf(dy, dy, fmaf(dz, dz, EPS_SOFT)));
            acc0 = fmaf(s.w, frsqrt(r2), acc0);
        }
        {
            const float4 s = site[t + d + 1];
            const float dx = px - s.x;
            const float dy = py - s.y;
            const float dz = pz - s.z;
            const float r2 = fmaf(dx, dx, fmaf(dy, dy, fmaf(dz, dz, EPS_SOFT)));
            acc1 = fmaf(s.w, frsqrt(r2), acc1);
        }
    }
    // d = 63 (all threads)
    {
        const float4 s = site[t + 63];
        const float dx = px - s.x;
        const float dy = py - s.y;
        const float dz = pz - s.z;
        const float r2 = fmaf(dx, dx, fmaf(dy, dy, fmaf(dz, dz, EPS_SOFT)));
        acc0 = fmaf(s.w, frsqrt(r2), acc0);
    }
    // d = 64 (threads 0..63 only: each opposite pair once)
    if (t < 64) {
        const float4 s = site[t + 64];
        const float dx = px - s.x;
        const float dy = py - s.y;
        const float dz = pz - s.z;
        const float r2 = fmaf(dx, dx, fmaf(dy, dy, fmaf(dz, dz, EPS_SOFT)));
        acc1 = fmaf(s.w, frsqrt(r2), acc1);
    }

    // Row charge applied once; lane -> warp -> CTA reduction
    float s = qi * (acc0 + acc1);
#pragma unroll
    for (int o = 16; o > 0; o >>= 1)
        s += __shfl_xor_sync(FULLMASK, s, o);

    const int warp = t >> 5;
    if ((t & 31) == 0) warp_sum[warp] = s;
    __syncthreads();
    if (t == 0)
        out[f] = (warp_sum[0] + warp_sum[1]) + (warp_sum[2] + warp_sum[3]);
}

extern "C" void kernel_launch(void* const* d_in, const int* in_sizes, int n_in,
                              void* d_out, int out_size) {
    const float* positions = (const float*)d_in[0];  // [N,3] f32
    const float* charges   = (const float*)d_in[1];  // [N]   f32
    float* out = (float*)d_out;                      // [B]   f32

    const int num_frames = out_size;                 // B
    interacting_sites_kernel<<<num_frames, S_SITES>>>(positions, charges, out);
}

// round 11
// speedup vs baseline: 1.1805x; 1.1779x over previous
#include <cuda_runtime.h>
#include <cstdint>

// InteractingSites: per-frame all-pairs soft-core Coulomb.
// R3-champion base + charge factoring + 128-bit triangle loads.
//
// energy[f] = sum_{i<j} q_i q_j * rsqrt(|p_i-p_j|^2 + 1e-6)
//
// CTA = 1 frame = 4 warps x 32. Tiles T0..T3 (32 sites each); lane l holds
// rows T0[l]..T3[l]; packed f32x2 row registers: ab=(T0,T1) ac=(T0,T2)
// cd=(T2,T3). Accumulators hold sum_j q_j * rsqrt(...) per row-stream; row
// charges applied once at the end.
//
// Enumeration (each unordered pair exactly once), split across 4 warps:
//  Rectangles (warp-uniform m -> BROADCAST LDS, 1 wavefront), warp w:
//    m in [8w, 8w+8):
//    g1: ab vs dup(T2[m])   g2: ab vs dup(T3[m])   g3: ac vs (T1[m],T3[m])
//  Triangles (lane-varying m=(l+dd)&31, 2x LDS.128):
//    warps 0..2: dd in [1+4w, 5+4w); warp 3: dd 13..15 + masked dd=16.

#define S_SITES 128
#define EPS2_PACKED 0x358637BD358637BDULL  // (1e-6f, 1e-6f)
#define FULLMASK 0xFFFFFFFFu

using u64 = unsigned long long;

__device__ __forceinline__ u64 pk2(float lo, float hi) {
    u64 r;
    asm("mov.b64 %0, {%1, %2};" : "=l"(r) : "f"(lo), "f"(hi));
    return r;
}
__device__ __forceinline__ void unpk2(u64 v, float& lo, float& hi) {
    asm("mov.b64 {%0, %1}, %2;" : "=f"(lo), "=f"(hi) : "l"(v));
}
__device__ __forceinline__ u64 add2(u64 a, u64 b) {
    u64 d;
    asm("add.rn.f32x2 %0, %1, %2;" : "=l"(d) : "l"(a), "l"(b));
    return d;
}
__device__ __forceinline__ u64 mul2(u64 a, u64 b) {
    u64 d;
    asm("mul.rn.f32x2 %0, %1, %2;" : "=l"(d) : "l"(a), "l"(b));
    return d;
}
__device__ __forceinline__ u64 fma2(u64 a, u64 b, u64 c) {
    u64 d;
    asm("fma.rn.f32x2 %0, %1, %2, %3;" : "=l"(d) : "l"(a), "l"(b), "l"(c));
    return d;
}
__device__ __forceinline__ u64 rsqrt2(u64 v) {
    float lo, hi;
    unpk2(v, lo, hi);
    float rl, rh;
    asm("rsqrt.approx.f32 %0, %1;" : "=f"(rl) : "f"(lo));
    asm("rsqrt.approx.f32 %0, %1;" : "=f"(rh) : "f"(hi));
    return pk2(rl, rh);
}

// rows (rx,ry,rz) vs j (jx,jy,jz negated, jq positive):
//   acc += jq * rsqrt(|row-j|^2 + eps)    (charge-factored)
__device__ __forceinline__ void pair_acc(u64 rx, u64 ry, u64 rz,
                                         u64 jx, u64 jy, u64 jz, u64 jq,
                                         u64& acc) {
    u64 dx = add2(rx, jx);
    u64 dy = add2(ry, jy);
    u64 dz = add2(rz, jz);
    u64 r2 = fma2(dz, dz, (u64)EPS2_PACKED);
    r2 = fma2(dy, dy, r2);
    r2 = fma2(dx, dx, r2);
    u64 rs = rsqrt2(r2);
    acc = fma2(jq, rs, acc);
}

__global__ __launch_bounds__(S_SITES)
void interacting_sites_kernel(const float* __restrict__ positions,
                              const float* __restrict__ charges,
                              float* __restrict__ out) {
    // AoS (broadcast, rect loop): [0:dupT2, 1:dupT3, 2:(T1,T3)][m][xx,yy,zz,qq]
    __shared__ u64 aos[3][32][4];
    // Triangle tables, 16B-paired for LDS.128:
    //   [0:(T0,T1), 1:(T2,T3)][m][0:(xx,yy), 1:(zz,qq)]
    __shared__ ulonglong2 soa[2][32][2];
    __shared__ float warp_sum[4];

    const int fid = blockIdx.x;
    const int w = threadIdx.x >> 5;
    const int l = threadIdx.x & 31;

    // Every warp loads the same 4x32 site table into registers
    const long long base = (long long)fid * S_SITES;
    float sx[4], sy[4], sz[4], sq[4];
#pragma unroll
    for (int k = 0; k < 4; ++k) {
        const long long idx = base + k * 32 + l;
        const float* p = positions + idx * 3;
        sx[k] = p[0];
        sy[k] = p[1];
        sz[k] = p[2];
        sq[k] = charges[idx];
    }

    // Warp 0 builds the j-tables (coords negated, charges positive)
    if (w == 0) {
        aos[0][l][0] = pk2(-sx[2], -sx[2]);
        aos[0][l][1] = pk2(-sy[2], -sy[2]);
        aos[0][l][2] = pk2(-sz[2], -sz[2]);
        aos[0][l][3] = pk2( sq[2],  sq[2]);
        aos[1][l][0] = pk2(-sx[3], -sx[3]);
        aos[1][l][1] = pk2(-sy[3], -sy[3]);
        aos[1][l][2] = pk2(-sz[3], -sz[3]);
        aos[1][l][3] = pk2( sq[3],  sq[3]);
        aos[2][l][0] = pk2(-sx[1], -sx[3]);
        aos[2][l][1] = pk2(-sy[1], -sy[3]);
        aos[2][l][2] = pk2(-sz[1], -sz[3]);
        aos[2][l][3] = pk2( sq[1],  sq[3]);
        soa[0][l][0] = make_ulonglong2(pk2(-sx[0], -sx[1]), pk2(-sy[0], -sy[1]));
        soa[0][l][1] = make_ulonglong2(pk2(-sz[0], -sz[1]), pk2( sq[0],  sq[1]));
        soa[1][l][0] = make_ulonglong2(pk2(-sx[2], -sx[3]), pk2(-sy[2], -sy[3]));
        soa[1][l][1] = make_ulonglong2(pk2(-sz[2], -sz[3]), pk2( sq[2],  sq[3]));
    }
    __syncthreads();

    const u64 ab_x = pk2(sx[0], sx[1]), ab_y = pk2(sy[0], sy[1]), ab_z = pk2(sz[0], sz[1]);
    const u64 ac_x = pk2(sx[0], sx[2]), ac_y = pk2(sy[0], sy[2]), ac_z = pk2(sz[0], sz[2]);
    const u64 cd_x = pk2(sx[2], sx[3]), cd_y = pk2(sy[2], sy[3]), cd_z = pk2(sz[2], sz[3]);
    const u64 ab_q = pk2(sq[0], sq[1]);
    const u64 ac_q = pk2(sq[0], sq[2]);
    const u64 cd_q = pk2(sq[2], sq[3]);

    u64 acc0 = 0ULL, acc1 = 0ULL, acc2 = 0ULL;

    // ── Rectangles: this warp handles m in [8w, 8w+8) — broadcast reads ──
    const int m0 = w << 3;
#pragma unroll
    for (int i = 0; i < 8; ++i) {
        const int m = m0 + i;
        {
            const ulonglong2 jxy = *reinterpret_cast<const ulonglong2*>(&aos[0][m][0]);
            const ulonglong2 jzq = *reinterpret_cast<const ulonglong2*>(&aos[0][m][2]);
            pair_acc(ab_x, ab_y, ab_z, jxy.x, jxy.y, jzq.x, jzq.y, acc0);
        }
        {
            const ulonglong2 jxy = *reinterpret_cast<const ulonglong2*>(&aos[1][m][0]);
            const ulonglong2 jzq = *reinterpret_cast<const ulonglong2*>(&aos[1][m][2]);
            pair_acc(ab_x, ab_y, ab_z, jxy.x, jxy.y, jzq.x, jzq.y, acc0);
        }
        {
            const ulonglong2 jxy = *reinterpret_cast<const ulonglong2*>(&aos[2][m][0]);
            const ulonglong2 jzq = *reinterpret_cast<const ulonglong2*>(&aos[2][m][2]);
            pair_acc(ac_x, ac_y, ac_z, jxy.x, jxy.y, jzq.x, jzq.y, acc1);
        }
    }

    // ── Triangles: warps 0..2 take dd in [1+4w,5+4w); warp 3: 13..15 + dd=16 ──
    const int dd0 = 1 + (w << 2);
#pragma unroll
    for (int i = 0; i < 4; ++i) {
        const int dd = dd0 + i;
        if (dd < 16) {
            const int m = (l + dd) & 31;
            const ulonglong2 a01 = soa[0][m][0];   // (xx, yy) of (T0,T1)
            const ulonglong2 b01 = soa[0][m][1];   // (zz, qq)
            pair_acc(ab_x, ab_y, ab_z, a01.x, a01.y, b01.x, b01.y, acc0);
            const ulonglong2 a23 = soa[1][m][0];
            const ulonglong2 b23 = soa[1][m][1];
            pair_acc(cd_x, cd_y, cd_z, a23.x, a23.y, b23.x, b23.y, acc2);
        }
    }
    if (w == 3 && l < 16) {   // dd = 16: each opposite pair once
        const int m = l + 16;
        const ulonglong2 a01 = soa[0][m][0];
        const ulonglong2 b01 = soa[0][m][1];
        pair_acc(ab_x, ab_y, ab_z, a01.x, a01.y, b01.x, b01.y, acc0);
        const ulonglong2 a23 = soa[1][m][0];
        const ulonglong2 b23 = soa[1][m][1];
        pair_acc(cd_x, cd_y, cd_z, a23.x, a23.y, b23.x, b23.y, acc2);
    }

    // Row charges applied once (packed), lane -> warp -> CTA reduction
    u64 t = mul2(ab_q, acc0);
    t = fma2(ac_q, acc1, t);
    t = fma2(cd_q, acc2, t);
    float tl, th;
    unpk2(t, tl, th);
    float s = tl + th;
#pragma unroll
    for (int o = 16; o > 0; o >>= 1)
        s += __shfl_xor_sync(FULLMASK, s, o);
    if (l == 0) warp_sum[w] = s;
    __syncthreads();
    if (threadIdx.x == 0)
        out[fid] = (warp_sum[0] + warp_sum[1]) + (warp_sum[2] + warp_sum[3]);
}

extern "C" void kernel_launch(void* const* d_in, const int* in_sizes, int n_in,
                              void* d_out, int out_size) {
    const float* positions = (const float*)d_in[0];  // [N,3] f32
    const float* charges   = (const float*)d_in[1];  // [N]   f32
    float* out = (float*)d_out;                      // [B]   f32

    const int num_frames = out_size;
    interacting_sites_kernel<<<num_frames, S_SITES>>>(positions, charges, out);
}

// round 12
// speedup vs baseline: 1.1834x; 1.0025x over previous
#include <cuda_runtime.h>
#include <cstdint>

// InteractingSites: per-frame all-pairs soft-core Coulomb.
// DUAL-FRAME f32x2 + LDS broadcast delivery.
//   f32x2 lo half = frame A, hi half = frame B. Same pair enumeration in both
//   halves -> every f32x2 op = one pair in each frame; every loaded j-quad
//   serves two real pairs (no dup() waste like the single-frame packed kernels).
//
// energy[f] = sum_{i<j} q_i q_j * rsqrt(|p_i-p_j|^2 + 1e-6)
//
// CTA = frame pair (A,B) = 4 warps x 32. Tiles T0..T3 (32 sites each).
// Shared table: site[tile][0][m] = (xA|xB, yA|yB), site[tile][1][m] = (zA|zB, qA|qB)
// (16B lane stride -> conflict-free LDS.128 for both lane-varying and broadcast).
// Lane l's rows: packed (Tk_A[l], Tk_B[l]) for k=0..3, read back from the table.
//
// Enumeration per frame (each unordered pair exactly once), split across warps:
//  Rectangles: m = 0..31, 6 tile combos (a<b): row tile a vs site[b][m].
//    Warp w: m in [8w, 8w+8).  (j is warp-uniform -> broadcast LDS)
//  Triangles: per tile k: row k vs site[k][(l+dd)&31], dd = 1..15 each once
//    + dd=16 masked to lanes 0..15. Warps 0..2: dd in [4w+1,4w+5); warp 3:
//    dd 13..15 + the masked dd=16.
//
// Charge factoring: acc_k += q_j * rsqrt (packed); row charges applied once.

#define S_SITES 128
#define EPS2_PACKED 0x358637BD358637BDULL  // (1e-6f, 1e-6f)
#define NEG1_PACKED 0xBF800000BF800000ULL  // (-1.0f, -1.0f)
#define FULLMASK 0xFFFFFFFFu

using u64 = unsigned long long;

__device__ __forceinline__ u64 pk2(float lo, float hi) {
    u64 r;
    asm("mov.b64 %0, {%1, %2};" : "=l"(r) : "f"(lo), "f"(hi));
    return r;
}
__device__ __forceinline__ void unpk2(u64 v, float& lo, float& hi) {
    asm("mov.b64 {%0, %1}, %2;" : "=f"(lo), "=f"(hi) : "l"(v));
}
__device__ __forceinline__ u64 fma2(u64 a, u64 b, u64 c) {
    u64 d;
    asm("fma.rn.f32x2 %0, %1, %2, %3;" : "=l"(d) : "l"(a), "l"(b), "l"(c));
    return d;
}
__device__ __forceinline__ u64 rsqrt2(u64 v) {
    float lo, hi;
    unpk2(v, lo, hi);
    float rl, rh;
    asm("rsqrt.approx.f32 %0, %1;" : "=f"(rl) : "f"(lo));
    asm("rsqrt.approx.f32 %0, %1;" : "=f"(rh) : "f"(hi));
    return pk2(rl, rh);
}

// acc += jq * rsqrt(|row - j|^2 + eps), elementwise on both frame halves.
__device__ __forceinline__ void grp(u64 rx, u64 ry, u64 rz,
                                    u64 jx, u64 jy, u64 jz, u64 jq,
                                    u64& acc) {
    u64 dx = fma2(jx, (u64)NEG1_PACKED, rx);
    u64 dy = fma2(jy, (u64)NEG1_PACKED, ry);
    u64 dz = fma2(jz, (u64)NEG1_PACKED, rz);
    u64 r2 = fma2(dz, dz, (u64)EPS2_PACKED);
    r2 = fma2(dy, dy, r2);
    r2 = fma2(dx, dx, r2);
    u64 rs = rsqrt2(r2);
    acc = fma2(jq, rs, acc);
}

__global__ __launch_bounds__(S_SITES)
void interacting_sites_kernel(const float* __restrict__ positions,
                              const float* __restrict__ charges,
                              float* __restrict__ out,
                              int num_frames) {
    // [tile][0:(xx,yy) | 1:(zz,qq)][m] — 16B lane stride, conflict-free
    __shared__ ulonglong2 site[4][2][32];
    __shared__ float warp_sumA[4];
    __shared__ float warp_sumB[4];

    const int w = threadIdx.x >> 5;
    const int l = threadIdx.x & 31;

    const int fidA = blockIdx.x * 2;
    const bool hasB = (fidA + 1) < num_frames;
    const int fidB = hasB ? fidA + 1 : fidA;

    // Warp w builds tile w's table entry for lane l (both frames)
    {
        const long long ia = (long long)fidA * S_SITES + w * 32 + l;
        const long long ib = (long long)fidB * S_SITES + w * 32 + l;
        const float* pa = positions + ia * 3;
        const float* pb = positions + ib * 3;
        const float qa = charges[ia];
        const float qb = charges[ib];
        site[w][0][l] = make_ulonglong2(pk2(pa[0], pb[0]), pk2(pa[1], pb[1]));
        site[w][1][l] = make_ulonglong2(pk2(pa[2], pb[2]), pk2(qa, qb));
    }
    __syncthreads();

    // Rows: lane l's packed sites for all 4 tiles (from the table)
    u64 rx[4], ry[4], rz[4], rq[4];
#pragma unroll
    for (int k = 0; k < 4; ++k) {
        const ulonglong2 u = site[k][0][l];
        const ulonglong2 v = site[k][1][l];
        rx[k] = u.x;
        ry[k] = u.y;
        rz[k] = v.x;
        rq[k] = v.y;
    }

    u64 acc[4] = {0ULL, 0ULL, 0ULL, 0ULL};

    // ── Rectangles: warp w handles m in [8w, 8w+8) — broadcast LDS ──
    const int m0 = w << 3;
#pragma unroll
    for (int i = 0; i < 8; ++i) {
        const int m = m0 + i;

        const ulonglong2 u1 = site[1][0][m], v1 = site[1][1][m];
        const ulonglong2 u2 = site[2][0][m], v2 = site[2][1][m];
        const ulonglong2 u3 = site[3][0][m], v3 = site[3][1][m];

        // 6 tile combos (a<b): row a vs j-site from tile b
        grp(rx[0], ry[0], rz[0], u1.x, u1.y, v1.x, v1.y, acc[0]);  // T0 x T1
        grp(rx[0], ry[0], rz[0], u2.x, u2.y, v2.x, v2.y, acc[0]);  // T0 x T2
        grp(rx[0], ry[0], rz[0], u3.x, u3.y, v3.x, v3.y, acc[0]);  // T0 x T3
        grp(rx[1], ry[1], rz[1], u2.x, u2.y, v2.x, v2.y, acc[1]);  // T1 x T2
        grp(rx[1], ry[1], rz[1], u3.x, u3.y, v3.x, v3.y, acc[1]);  // T1 x T3
        grp(rx[2], ry[2], rz[2], u3.x, u3.y, v3.x, v3.y, acc[2]);  // T2 x T3
    }

    // ── Triangles: warps 0..2 take dd in [4w+1,4w+5); warp 3: 13..15 + dd=16 ──
    const int dd0 = 1 + (w << 2);
#pragma unroll
    for (int i = 0; i < 4; ++i) {
        const int dd = dd0 + i;
        if (dd < 16) {
            const int m = (l + dd) & 31;
#pragma unroll
            for (int k = 0; k < 4; ++k) {
                const ulonglong2 u = site[k][0][m];
                const ulonglong2 v = site[k][1][m];
                grp(rx[k], ry[k], rz[k], u.x, u.y, v.x, v.y, acc[k]);
            }
        }
    }
    if (w == 3 && l < 16) {   // dd = 16: each opposite pair once
        const int m = l + 16;
#pragma unroll
        for (int k = 0; k < 4; ++k) {
            const ulonglong2 u = site[k][0][m];
            const ulonglong2 v = site[k][1][m];
            grp(rx[k], ry[k], rz[k], u.x, u.y, v.x, v.y, acc[k]);
        }
    }

    // Row charges applied once (packed); split halves; reduce
    u64 e = fma2(rq[0], acc[0], 0ULL);
    e = fma2(rq[1], acc[1], e);
    e = fma2(rq[2], acc[2], e);
    e = fma2(rq[3], acc[3], e);
    float eA, eB;
    unpk2(e, eA, eB);
#pragma unroll
    for (int o = 16; o > 0; o >>= 1) {
        eA += __shfl_xor_sync(FULLMASK, eA, o);
        eB += __shfl_xor_sync(FULLMASK, eB, o);
    }
    if (l == 0) {
        warp_sumA[w] = eA;
        warp_sumB[w] = eB;
    }
    __syncthreads();
    if (threadIdx.x == 0) {
        out[fidA] = (warp_sumA[0] + warp_sumA[1]) + (warp_sumA[2] + warp_sumA[3]);
        if (hasB)
            out[fidB] = (warp_sumB[0] + warp_sumB[1]) + (warp_sumB[2] + warp_sumB[3]);
    }
}

extern "C" void kernel_launch(void* const* d_in, const int* in_sizes, int n_in,
                              void* d_out, int out_size) {
    const float* positions = (const float*)d_in[0];  // [N,3] f32
    const float* charges   = (const float*)d_in[1];  // [N]   f32
    float* out = (float*)d_out;                      // [B]   f32

    const int num_frames = out_size;
    const int grid = (num_frames + 1) / 2;
    interacting_sites_kernel<<<grid, S_SITES>>>(positions, charges, out, num_frames);
}